// round 15
// baseline (speedup 1.0000x reference)
#include <cuda_runtime.h>
#include <cuda_fp16.h>
#include <cstdint>

#define LDIM      256
#define BM        128
#define KC        64
#define NCH       4              // 256/64
#define NTHREADS  1024

// ---- byte layout (identical to R11/R14) ----
#define A_BYTES    (128 * 128)            // 16KB
#define B_BYTES    (256 * 128)            // 32KB
#define STAGE_B    (A_BYTES + B_BYTES)    // 48KB
#define WPKB       (2 * STAGE_B)          // 98304 : packed tree weights, 255*16B
#define SREDB      (WPKB + 4096)          // 102400 : 128*9 floats
#define SMEM_BYTES (SREDB + 4736)         // 107136
// p1 plane (128 x 132 floats) aliases the stage region after the mainloop

#define P1STRIDE 132
#define EPS 1e-6f

__device__ __half2 g_Wh[LDIM * LDIM / 2];

// ---------------- helpers ----------------
// exact sigmoid (lambda table + final output only)
__device__ __forceinline__ float sigf(float z) {
    float e = __expf(-z);
    float r;
    asm("rcp.approx.f32 %0, %1;" : "=f"(r) : "f"(1.0f + e));
    return r;
}

// fast leaf sigmoid: sigmoid(c - 2) = 0.5*tanh(0.5c - 1) + 0.5  (1 MUFU)
__device__ __forceinline__ float sig_leaf(float c) {
    float t;
    asm("tanh.approx.f32 %0, %1;" : "=f"(t) : "f"(fmaf(c, 0.5f, -1.0f)));
    return fmaf(t, 0.5f, 0.5f);
}

// valid for l,r,w1,w2 > 0; w = {w1, w2, lam, 1-lam}
__device__ __forceinline__ float gcdop4(float l, float r, float4 w) {
    float a  = l * w.x;
    float b  = r * w.y;
    float mn = fminf(a, b);
    float mx = fmaxf(a, b);
    return fmaf(w.w, mx, fmaf(w.z, mn, EPS));
}

__device__ __forceinline__ void hmma16(float c[4],
                                       uint32_t a0, uint32_t a1, uint32_t a2, uint32_t a3,
                                       uint32_t b0, uint32_t b1) {
    asm volatile(
        "mma.sync.aligned.m16n8k16.row.col.f32.f16.f16.f32 "
        "{%0,%1,%2,%3},{%4,%5,%6,%7},{%8,%9},{%0,%1,%2,%3};"
        : "+f"(c[0]), "+f"(c[1]), "+f"(c[2]), "+f"(c[3])
        : "r"(a0), "r"(a1), "r"(a2), "r"(a3), "r"(b0), "r"(b1));
}

__device__ __forceinline__ void ldsm_x4(uint32_t r[4], uint32_t addr) {
    asm volatile("ldmatrix.sync.aligned.m8n8.x4.shared.b16 {%0,%1,%2,%3}, [%4];"
                 : "=r"(r[0]), "=r"(r[1]), "=r"(r[2]), "=r"(r[3]) : "r"(addr));
}

__device__ __forceinline__ uint32_t smem_u32(const void* p) {
    uint32_t a;
    asm("{ .reg .u64 t; cvta.to.shared.u64 t, %1; cvt.u32.u64 %0, t; }" : "=r"(a) : "l"(p));
    return a;
}

__device__ __forceinline__ void cp16(uint32_t s, const void* g) {
    uint64_t ga = __cvta_generic_to_global(g);
    asm volatile("cp.async.cg.shared.global [%0], [%1], 16;" :: "r"(s), "l"(ga));
}

// ---------------- W -> fp16 pre-pass (vectorized) ----------------
__global__ void conv_w_kernel(const float* __restrict__ W) {
    int i = blockIdx.x * 256 + threadIdx.x;     // 16384 x float4
    float4 v = ((const float4*)W)[i];
    __half2 h0 = __floats2half2_rn(v.x, v.y);
    __half2 h1 = __floats2half2_rn(v.z, v.w);
    uint2 u;
    u.x = *(uint32_t*)&h0;
    u.y = *(uint32_t*)&h1;
    ((uint2*)g_Wh)[i] = u;
}

// ---------------- staging (identical to R11/R14) ----------------
__device__ __forceinline__ uint4 ldA(const float* __restrict__ x, int row0, int c,
                                     int r, int q) {
    const float4* gp = (const float4*)(x + (size_t)(row0 + r) * LDIM + c * KC + q * 8);
    float4 f0 = __ldcs(gp);
    float4 f1 = __ldcs(gp + 1);
    uint4 u; __half2 h;
    h = __floats2half2_rn(f0.x, f0.y); u.x = *(uint32_t*)&h;
    h = __floats2half2_rn(f0.z, f0.w); u.y = *(uint32_t*)&h;
    h = __floats2half2_rn(f1.x, f1.y); u.z = *(uint32_t*)&h;
    h = __floats2half2_rn(f1.z, f1.w); u.w = *(uint32_t*)&h;
    return u;
}

__device__ __forceinline__ void stA(char* sm, int buf, uint4 u, int r, int q) {
    char* base = sm + (size_t)buf * STAGE_B + (size_t)r * 128;
    *(uint4*)(base + ((q ^ (r & 7)) * 16)) = u;
}

__device__ __forceinline__ void cpB(uint32_t sbase, int buf, int c, int tid) {
    int n = tid >> 2, qq = tid & 3;
    int s = n & 7;
    uint32_t brow = sbase + (uint32_t)buf * STAGE_B + A_BYTES + (uint32_t)n * 128u;
    const __half* g = (const __half*)g_Wh + (size_t)n * LDIM + c * KC + qq * 16;
    cp16(brow + (uint32_t)(((2 * qq)     ^ s) * 16), g);
    cp16(brow + (uint32_t)(((2 * qq + 1) ^ s) * 16), g + 8);
    asm volatile("cp.async.commit_group;");
}

// ---------------- main kernel ----------------
__global__ void __launch_bounds__(NTHREADS, 1)
btln_main_kernel(const float* __restrict__ x,
                 const float* __restrict__ wts,
                 const float* __restrict__ bias,
                 const float* __restrict__ w_out,
                 const float* __restrict__ b_out,
                 float* __restrict__ out)
{
    extern __shared__ char sm[];
    float*  p1f  = (float*)sm;                 // epilogue plane, aliases staging
    float4* wpk  = (float4*)(sm + WPKB);
    float*  sred = (float*)(sm + SREDB);
    const uint32_t sbase = smem_u32(sm);

    const int tid  = threadIdx.x;
    const int lane = tid & 31;
    const int wid  = tid >> 5;            // 0..31
    const int gid  = lane >> 2;
    const int tig  = lane & 3;
    const int wn   = wid & 3;             // N band of 64 cols
    const int wm   = wid >> 2;            // M band of 16 rows (0..7)
    const int row0 = blockIdx.x * BM;
    const int ar_r = tid >> 3;            // staging row 0..127
    const int ar_q = tid & 7;

    if (tid < 255) {
        float l = sigf(bias[tid]);
        wpk[tid] = make_float4(wts[2 * tid], wts[2 * tid + 1], l, 1.0f - l);
    }

    float cacc[8][4];
    #pragma unroll
    for (int nt = 0; nt < 8; nt++)
        #pragma unroll
        for (int i = 0; i < 4; i++) cacc[nt][i] = 0.0f;

    // prologue: stage chunk 0
    {
        uint4 a0 = ldA(x, row0, 0, ar_r, ar_q);
        cpB(sbase, 0, 0, tid);
        stA(sm, 0, a0, ar_r, ar_q);
    }

    // ---- loop-invariant fragment addressing ----
    const int a_rl = lane & 15;
    const int a_ch = lane >> 4;
    const int b_rl = ((lane >> 4) << 3) | (lane & 7);
    const int b_ch = (lane >> 3) & 1;

    const int      rowA  = wm * 16 + a_rl;
    const uint32_t aBase = (uint32_t)rowA * 128u;            // + sbase + buf later
    const int      aPar  = rowA & 7;

    uint32_t bBase[4];
    int      bPar[4];
    #pragma unroll
    for (int ntp = 0; ntp < 4; ntp++) {
        int rowB   = wn * 64 + ntp * 16 + b_rl;
        bBase[ntp] = A_BYTES + (uint32_t)rowB * 128u;
        bPar[ntp]  = rowB & 7;
    }

    #pragma unroll 1
    for (int c = 0; c < NCH; c++) {
        const int buf = c & 1;
        uint4 an;
        if (c + 1 < NCH) {
            cpB(sbase, buf ^ 1, c + 1, tid);
            an = ldA(x, row0, c + 1, ar_r, ar_q);
            asm volatile("cp.async.wait_group 1;" ::: "memory");
        } else {
            asm volatile("cp.async.wait_group 0;" ::: "memory");
        }
        __syncthreads();

        const uint32_t stg = sbase + (uint32_t)buf * STAGE_B;

        #pragma unroll
        for (int ks = 0; ks < 4; ks++) {
            // ---- batch ALL loads for this ks: latencies overlap ----
            uint32_t a[4];
            ldsm_x4(a, stg + aBase + (uint32_t)(((ks * 2 + a_ch) ^ aPar) * 16));
            uint32_t b[4][4];
            #pragma unroll
            for (int ntp = 0; ntp < 4; ntp++)
                ldsm_x4(b[ntp], stg + bBase[ntp]
                                + (uint32_t)(((ks * 2 + b_ch) ^ bPar[ntp]) * 16));
            // ---- then batch the math: single stall at the head ----
            #pragma unroll
            for (int ntp = 0; ntp < 4; ntp++) {
                hmma16(cacc[2 * ntp],     a[0], a[1], a[2], a[3], b[ntp][0], b[ntp][1]);
                hmma16(cacc[2 * ntp + 1], a[0], a[1], a[2], a[3], b[ntp][2], b[ntp][3]);
            }
        }

        if (c + 1 < NCH) stA(sm, buf ^ 1, an, ar_r, ar_q);
        // next iteration's __syncthreads orders stA
    }

    // all LDSM reads of staging done before p1 stores overwrite it
    __syncthreads();

    // -------- phase 1: leaf sigmoid (tanh.approx) + L1 -> p1[row][node] --------
    #pragma unroll
    for (int nt = 0; nt < 8; nt++) {
        int j = wn * 32 + nt * 4 + tig;
        float4 w = wpk[j];
        #pragma unroll
        for (int rw = 0; rw < 2; rw++) {
            float l = sig_leaf(cacc[nt][rw * 2]);
            float r = sig_leaf(cacc[nt][rw * 2 + 1]);
            int row = wm * 16 + gid + rw * 8;
            p1f[row * P1STRIDE + j] = gcdop4(l, r, w);
        }
    }
    __syncthreads();

    // -------- phase 2: one octant subtree per thread (L2..L5) --------
    {
        const int row = tid & 127;
        const int oct = tid >> 7;
        const float4* vp = (const float4*)(p1f + row * P1STRIDE + oct * 16);
        float4 q0 = vp[0], q1 = vp[1], q2 = vp[2], q3 = vp[3];
        float v[16] = {q0.x,q0.y,q0.z,q0.w, q1.x,q1.y,q1.z,q1.w,
                       q2.x,q2.y,q2.z,q2.w, q3.x,q3.y,q3.z,q3.w};
        float t2[8];
        #pragma unroll
        for (int i = 0; i < 8; i++)
            t2[i] = gcdop4(v[2*i], v[2*i+1], wpk[128 + oct * 8 + i]);
        float t3[4];
        #pragma unroll
        for (int i = 0; i < 4; i++)
            t3[i] = gcdop4(t2[2*i], t2[2*i+1], wpk[192 + oct * 4 + i]);
        float t4[2];
        #pragma unroll
        for (int i = 0; i < 2; i++)
            t4[i] = gcdop4(t3[2*i], t3[2*i+1], wpk[224 + oct * 2 + i]);
        sred[row * 9 + oct] = gcdop4(t4[0], t4[1], wpk[240 + oct]);
    }
    __syncthreads();

    // -------- phase 3: L6..L8 + output sigmoid (exact) --------
    if (tid < BM) {
        const float* s = sred + tid * 9;
        float t6a = gcdop4(s[0], s[1], wpk[248]);
        float t6b = gcdop4(s[2], s[3], wpk[249]);
        float t6c = gcdop4(s[4], s[5], wpk[250]);
        float t6d = gcdop4(s[6], s[7], wpk[251]);
        float t7a = gcdop4(t6a, t6b, wpk[252]);
        float t7b = gcdop4(t6c, t6d, wpk[253]);
        float root = gcdop4(t7a, t7b, wpk[254]);
        out[row0 + tid] = sigf(fmaf(root, w_out[0], b_out[0]));
    }
}

extern "C" void kernel_launch(void* const* d_in, const int* in_sizes, int n_in,
                              void* d_out, int out_size) {
    const float* x     = (const float*)d_in[0];
    const float* W     = (const float*)d_in[1];
    const float* wts   = (const float*)d_in[2];
    const float* bias  = (const float*)d_in[3];
    const float* w_out = (const float*)d_in[4];
    const float* b_out = (const float*)d_in[5];
    float* out = (float*)d_out;

    const int Brows = in_sizes[0] / LDIM;   // 65536
    const int grid  = Brows / BM;           // 512

    conv_w_kernel<<<LDIM * LDIM / 4 / 256, 256>>>(W);

    cudaFuncSetAttribute(btln_main_kernel,
                         cudaFuncAttributeMaxDynamicSharedMemorySize, SMEM_BYTES);
    btln_main_kernel<<<grid, NTHREADS, SMEM_BYTES>>>(x, wts, bias, w_out, b_out, out);
}

// round 16
// speedup vs baseline: 1.0416x; 1.0416x over previous
#include <cuda_runtime.h>
#include <cuda_fp16.h>
#include <cstdint>

#define LDIM      256
#define BM        64             // rows per CTA (2 CTAs/SM)
#define KC        64
#define NCH       4              // 256/64
#define NTHREADS  512

// ---- byte layout ----
#define A_BYTES    (64 * 128)             // 8KB
#define B_BYTES    (256 * 128)            // 32KB
#define STAGE_B    (A_BYTES + B_BYTES)    // 40KB
#define WPKB       (2 * STAGE_B)          // 81920 : packed tree weights, 255*16B
#define SREDB      (WPKB + 4096)          // 86016 : 64*9 floats
#define SMEM_BYTES (SREDB + 2304)         // 88320
// p1 plane (64 x 132 floats = 33792B) aliases the stage region after the mainloop

#define P1STRIDE 132
#define EPS 1e-6f

__device__ __half2 g_Wh[LDIM * LDIM / 2];

// ---------------- helpers ----------------
// exact sigmoid (lambda table + final output only)
__device__ __forceinline__ float sigf(float z) {
    float e = __expf(-z);
    float r;
    asm("rcp.approx.f32 %0, %1;" : "=f"(r) : "f"(1.0f + e));
    return r;
}

// fast leaf sigmoid: sigmoid(c - 2) = 0.5*tanh(0.5c - 1) + 0.5  (1 MUFU)
__device__ __forceinline__ float sig_leaf(float c) {
    float t;
    asm("tanh.approx.f32 %0, %1;" : "=f"(t) : "f"(fmaf(c, 0.5f, -1.0f)));
    return fmaf(t, 0.5f, 0.5f);
}

// valid for l,r,w1,w2 > 0; w = {w1, w2, lam, 1-lam}
__device__ __forceinline__ float gcdop4(float l, float r, float4 w) {
    float a  = l * w.x;
    float b  = r * w.y;
    float mn = fminf(a, b);
    float mx = fmaxf(a, b);
    return fmaf(w.w, mx, fmaf(w.z, mn, EPS));
}

__device__ __forceinline__ void hmma16(float c[4],
                                       uint32_t a0, uint32_t a1, uint32_t a2, uint32_t a3,
                                       uint32_t b0, uint32_t b1) {
    asm volatile(
        "mma.sync.aligned.m16n8k16.row.col.f32.f16.f16.f32 "
        "{%0,%1,%2,%3},{%4,%5,%6,%7},{%8,%9},{%0,%1,%2,%3};"
        : "+f"(c[0]), "+f"(c[1]), "+f"(c[2]), "+f"(c[3])
        : "r"(a0), "r"(a1), "r"(a2), "r"(a3), "r"(b0), "r"(b1));
}

__device__ __forceinline__ void ldsm_x4(uint32_t r[4], uint32_t addr) {
    asm volatile("ldmatrix.sync.aligned.m8n8.x4.shared.b16 {%0,%1,%2,%3}, [%4];"
                 : "=r"(r[0]), "=r"(r[1]), "=r"(r[2]), "=r"(r[3]) : "r"(addr));
}

__device__ __forceinline__ uint32_t smem_u32(const void* p) {
    uint32_t a;
    asm("{ .reg .u64 t; cvta.to.shared.u64 t, %1; cvt.u32.u64 %0, t; }" : "=r"(a) : "l"(p));
    return a;
}

__device__ __forceinline__ void cp16(uint32_t s, const void* g) {
    uint64_t ga = __cvta_generic_to_global(g);
    asm volatile("cp.async.cg.shared.global [%0], [%1], 16;" :: "r"(s), "l"(ga));
}

// ---------------- W -> fp16 pre-pass (vectorized) ----------------
__global__ void conv_w_kernel(const float* __restrict__ W) {
    int i = blockIdx.x * 256 + threadIdx.x;     // 16384 x float4
    float4 v = ((const float4*)W)[i];
    __half2 h0 = __floats2half2_rn(v.x, v.y);
    __half2 h1 = __floats2half2_rn(v.z, v.w);
    uint2 u;
    u.x = *(uint32_t*)&h0;
    u.y = *(uint32_t*)&h1;
    ((uint2*)g_Wh)[i] = u;
}

// ---------------- staging ----------------
// A: each thread stages 8 halves. r = tid>>3 (0..63), q = tid&7.
__device__ __forceinline__ uint4 ldA(const float* __restrict__ x, int row0, int c,
                                     int r, int q) {
    const float4* gp = (const float4*)(x + (size_t)(row0 + r) * LDIM + c * KC + q * 8);
    float4 f0 = __ldcs(gp);
    float4 f1 = __ldcs(gp + 1);
    uint4 u; __half2 h;
    h = __floats2half2_rn(f0.x, f0.y); u.x = *(uint32_t*)&h;
    h = __floats2half2_rn(f0.z, f0.w); u.y = *(uint32_t*)&h;
    h = __floats2half2_rn(f1.x, f1.y); u.z = *(uint32_t*)&h;
    h = __floats2half2_rn(f1.z, f1.w); u.w = *(uint32_t*)&h;
    return u;
}

__device__ __forceinline__ void stA(char* sm, int buf, uint4 u, int r, int q) {
    char* base = sm + (size_t)buf * STAGE_B + (size_t)r * 128;
    *(uint4*)(base + ((q ^ (r & 7)) * 16)) = u;
}

// B: 256 rows x 128B; each thread stages a half-row (4 cp16).
__device__ __forceinline__ void cpB(uint32_t sbase, int buf, int c, int tid) {
    int n = tid >> 1, h = tid & 1;
    int s = n & 7;
    uint32_t brow = sbase + (uint32_t)buf * STAGE_B + A_BYTES + (uint32_t)n * 128u;
    const __half* g = (const __half*)g_Wh + (size_t)n * LDIM + c * KC + h * 32;
    #pragma unroll
    for (int j = 0; j < 4; j++)
        cp16(brow + (uint32_t)(((h * 4 + j) ^ s) * 16), g + j * 8);
    asm volatile("cp.async.commit_group;");
}

// ---------------- main kernel ----------------
__global__ void __launch_bounds__(NTHREADS, 2)
btln_main_kernel(const float* __restrict__ x,
                 const float* __restrict__ wts,
                 const float* __restrict__ bias,
                 const float* __restrict__ w_out,
                 const float* __restrict__ b_out,
                 float* __restrict__ out)
{
    extern __shared__ char sm[];
    float*  p1f  = (float*)sm;                 // epilogue plane, aliases staging
    float4* wpk  = (float4*)(sm + WPKB);
    float*  sred = (float*)(sm + SREDB);
    const uint32_t sbase = smem_u32(sm);

    const int tid  = threadIdx.x;
    const int lane = tid & 31;
    const int wid  = tid >> 5;            // 0..15
    const int gid  = lane >> 2;
    const int tig  = lane & 3;
    const int wn   = wid & 3;             // N band of 64 cols
    const int wm   = wid >> 2;            // M band of 16 rows (0..3)
    const int row0 = blockIdx.x * BM;
    const int ar_r = tid >> 3;            // A staging row 0..63
    const int ar_q = tid & 7;

    if (tid < 255) {
        float l = sigf(bias[tid]);
        wpk[tid] = make_float4(wts[2 * tid], wts[2 * tid + 1], l, 1.0f - l);
    }

    float cacc[8][4];
    #pragma unroll
    for (int nt = 0; nt < 8; nt++)
        #pragma unroll
        for (int i = 0; i < 4; i++) cacc[nt][i] = 0.0f;

    // prologue: stage chunk 0
    {
        uint4 a0 = ldA(x, row0, 0, ar_r, ar_q);
        cpB(sbase, 0, 0, tid);
        stA(sm, 0, a0, ar_r, ar_q);
    }

    // ---- loop-invariant fragment addressing ----
    const int a_rl = lane & 15;
    const int a_ch = lane >> 4;
    const int b_rl = ((lane >> 4) << 3) | (lane & 7);
    const int b_ch = (lane >> 3) & 1;

    const int      rowA  = wm * 16 + a_rl;
    const uint32_t aBase = (uint32_t)rowA * 128u;
    const int      aPar  = rowA & 7;

    uint32_t bBase[4];
    int      bPar[4];
    #pragma unroll
    for (int ntp = 0; ntp < 4; ntp++) {
        int rowB   = wn * 64 + ntp * 16 + b_rl;
        bBase[ntp] = A_BYTES + (uint32_t)rowB * 128u;
        bPar[ntp]  = rowB & 7;
    }

    #pragma unroll 1
    for (int c = 0; c < NCH; c++) {
        const int buf = c & 1;
        uint4 an;
        if (c + 1 < NCH) {
            cpB(sbase, buf ^ 1, c + 1, tid);
            an = ldA(x, row0, c + 1, ar_r, ar_q);
            asm volatile("cp.async.wait_group 1;" ::: "memory");
        } else {
            asm volatile("cp.async.wait_group 0;" ::: "memory");
        }
        __syncthreads();

        const uint32_t stg = sbase + (uint32_t)buf * STAGE_B;

        #pragma unroll
        for (int ks = 0; ks < 4; ks++) {
            uint32_t a[4];
            ldsm_x4(a, stg + aBase + (uint32_t)(((ks * 2 + a_ch) ^ aPar) * 16));
            uint32_t b[4][4];
            #pragma unroll
            for (int ntp = 0; ntp < 4; ntp++)
                ldsm_x4(b[ntp], stg + bBase[ntp]
                                + (uint32_t)(((ks * 2 + b_ch) ^ bPar[ntp]) * 16));
            #pragma unroll
            for (int ntp = 0; ntp < 4; ntp++) {
                hmma16(cacc[2 * ntp],     a[0], a[1], a[2], a[3], b[ntp][0], b[ntp][1]);
                hmma16(cacc[2 * ntp + 1], a[0], a[1], a[2], a[3], b[ntp][2], b[ntp][3]);
            }
        }

        if (c + 1 < NCH) stA(sm, buf ^ 1, an, ar_r, ar_q);
        // next iteration's __syncthreads orders stA
    }

    // all LDSM reads of staging done before p1 stores overwrite it
    __syncthreads();

    // -------- phase 1: leaf sigmoid (tanh.approx) + L1 -> p1[row][node] --------
    #pragma unroll
    for (int nt = 0; nt < 8; nt++) {
        int j = wn * 32 + nt * 4 + tig;
        float4 w = wpk[j];
        #pragma unroll
        for (int rw = 0; rw < 2; rw++) {
            float l = sig_leaf(cacc[nt][rw * 2]);
            float r = sig_leaf(cacc[nt][rw * 2 + 1]);
            int row = wm * 16 + gid + rw * 8;
            p1f[row * P1STRIDE + j] = gcdop4(l, r, w);
        }
    }
    __syncthreads();

    // -------- phase 2: one octant subtree per thread (L2..L5) --------
    // 512 threads = 64 rows x 8 octants, exact cover
    {
        const int row = tid & 63;
        const int oct = tid >> 6;          // 0..7
        const float4* vp = (const float4*)(p1f + row * P1STRIDE + oct * 16);
        float4 q0 = vp[0], q1 = vp[1], q2 = vp[2], q3 = vp[3];
        float v[16] = {q0.x,q0.y,q0.z,q0.w, q1.x,q1.y,q1.z,q1.w,
                       q2.x,q2.y,q2.z,q2.w, q3.x,q3.y,q3.z,q3.w};
        float t2[8];
        #pragma unroll
        for (int i = 0; i < 8; i++)
            t2[i] = gcdop4(v[2*i], v[2*i+1], wpk[128 + oct * 8 + i]);
        float t3[4];
        #pragma unroll
        for (int i = 0; i < 4; i++)
            t3[i] = gcdop4(t2[2*i], t2[2*i+1], wpk[192 + oct * 4 + i]);
        float t4[2];
        #pragma unroll
        for (int i = 0; i < 2; i++)
            t4[i] = gcdop4(t3[2*i], t3[2*i+1], wpk[224 + oct * 2 + i]);
        sred[row * 9 + oct] = gcdop4(t4[0], t4[1], wpk[240 + oct]);
    }
    __syncthreads();

    // -------- phase 3: L6..L8 + output sigmoid (exact, 64 threads) --------
    if (tid < BM) {
        const float* s = sred + tid * 9;
        float t6a = gcdop4(s[0], s[1], wpk[248]);
        float t6b = gcdop4(s[2], s[3], wpk[249]);
        float t6c = gcdop4(s[4], s[5], wpk[250]);
        float t6d = gcdop4(s[6], s[7], wpk[251]);
        float t7a = gcdop4(t6a, t6b, wpk[252]);
        float t7b = gcdop4(t6c, t6d, wpk[253]);
        float root = gcdop4(t7a, t7b, wpk[254]);
        out[row0 + tid] = sigf(fmaf(root, w_out[0], b_out[0]));
    }
}

extern "C" void kernel_launch(void* const* d_in, const int* in_sizes, int n_in,
                              void* d_out, int out_size) {
    const float* x     = (const float*)d_in[0];
    const float* W     = (const float*)d_in[1];
    const float* wts   = (const float*)d_in[2];
    const float* bias  = (const float*)d_in[3];
    const float* w_out = (const float*)d_in[4];
    const float* b_out = (const float*)d_in[5];
    float* out = (float*)d_out;

    const int Brows = in_sizes[0] / LDIM;   // 65536
    const int grid  = Brows / BM;           // 1024

    conv_w_kernel<<<LDIM * LDIM / 4 / 256, 256>>>(W);

    cudaFuncSetAttribute(btln_main_kernel,
                         cudaFuncAttributeMaxDynamicSharedMemorySize, SMEM_BYTES);
    btln_main_kernel<<<grid, NTHREADS, SMEM_BYTES>>>(x, wts, bias, w_out, b_out, out);
}